// round 6
// baseline (speedup 1.0000x reference)
#include <cuda_runtime.h>

#define N_NODES 50000
#define N_EDGES 800000
#define H 64
#define RES 0.5f
#define INV_1PRES (1.0f / (1.0f + RES))

// ---------------- device scratch (no allocation allowed) ----------------
__device__ float g_s1[N_NODES];
__device__ float g_s2[N_NODES];      // att_b folded in
__device__ float g_rowsum[N_NODES];
__device__ float g_expatt[N_EDGES];

typedef unsigned long long u64;

__device__ __forceinline__ u64 pack2(float lo, float hi) {
    u64 r;
    asm("mov.b64 %0, {%1, %2};" : "=l"(r) : "f"(lo), "f"(hi));
    return r;
}
__device__ __forceinline__ void unpack2(u64 v, float& lo, float& hi) {
    asm("mov.b64 {%0, %1}, %2;" : "=f"(lo), "=f"(hi) : "l"(v));
}
__device__ __forceinline__ u64 ffma2(u64 a, u64 b, u64 c) {
    u64 d;
    asm("fma.rn.f32x2 %0, %1, %2, %3;" : "=l"(d) : "l"(a), "l"(b), "l"(c));
    return d;
}

// ------------------------------------------------------------------------
// Kernel 1: tiled dual-GEMM for per-node attention scalars, TWO-PASS:
//   pass A: acc = X@W1 -> p1 scalars; pass B reuses the same registers for
//   X@W2 -> p2. Peak live accumulators halved -> 3 blocks/SM.
//   Block(256) = 128-node tile. Thread (ng=tid&31, cg=tid>>5):
//   4 nodes x 8 cols in f32x2 regs per pass. Conflict-free smem transpose.
// ------------------------------------------------------------------------
__global__ __launch_bounds__(256, 3)
void gat_node_kernel(const float* __restrict__ embeds,
                     const float* __restrict__ W1, const float* __restrict__ b1,
                     const float* __restrict__ W2, const float* __restrict__ b2,
                     const float* __restrict__ att_w, const float* __restrict__ att_b) {
    extern __shared__ float smem[];
    float* Xs  = smem;            // [64 k][128 nodes]  = 8192 floats (32KB)
    float* W1s = smem + 8192;     // [64 k][64 j]       = 4096 floats (16KB)
    float* W2s = smem + 12288;    // 16KB

    const int tid = threadIdx.x;
    const int tile = blockIdx.x * 128;
    const int ng = tid & 31;   // nodes 4*ng .. 4*ng+3
    const int cg = tid >> 5;   // cols cg*8 .. cg*8+7 (uniform per warp)

    // ---- load W1, W2 (coalesced float4 copies) ----
    {
        const float4* w1g = (const float4*)W1;
        const float4* w2g = (const float4*)W2;
        float4* w1s = (float4*)W1s;
        float4* w2s = (float4*)W2s;
#pragma unroll
        for (int i = 0; i < 4; i++) {
            int idx = tid + i * 256;
            w1s[idx] = w1g[idx];
            w2s[idx] = w2g[idx];
        }
    }
    // ---- load X tile -> k-major smem, conflict-free STS ----
    {
#pragma unroll
        for (int i = 0; i < 8; i++) {
            int idx = tid + i * 256;          // [0, 2048)
            int nl = idx & 127;
            int k4 = idx >> 7;                // 0..15
            int node = tile + nl;
            if (node > N_NODES - 1) node = N_NODES - 1;
            float4 v = __ldg((const float4*)(embeds + (size_t)node * H + k4 * 4));
            Xs[(4 * k4 + 0) * 128 + nl] = v.x;
            Xs[(4 * k4 + 1) * 128 + nl] = v.y;
            Xs[(4 * k4 + 2) * 128 + nl] = v.z;
            Xs[(4 * k4 + 3) * 128 + nl] = v.w;
        }
    }
    __syncthreads();

    float p1[4], p2[4];
    u64 acc[4][4];

    // ================= pass A: X @ W1 =================
#pragma unroll
    for (int n = 0; n < 4; n++)
#pragma unroll
        for (int j = 0; j < 4; j++) acc[n][j] = 0ULL;

#pragma unroll 4
    for (int k = 0; k < 64; k++) {
        float4 xv = *(const float4*)(Xs + k * 128 + ng * 4);
        u64 xp[4];
        xp[0] = pack2(xv.x, xv.x);
        xp[1] = pack2(xv.y, xv.y);
        xp[2] = pack2(xv.z, xv.z);
        xp[3] = pack2(xv.w, xv.w);
        const float* wr = W1s + k * 64 + cg * 8;    // warp-uniform broadcast
        ulonglong2 wa = *(const ulonglong2*)(wr);
        ulonglong2 wb = *(const ulonglong2*)(wr + 4);
#pragma unroll
        for (int n = 0; n < 4; n++) {
            acc[n][0] = ffma2(xp[n], wa.x, acc[n][0]);
            acc[n][1] = ffma2(xp[n], wa.y, acc[n][1]);
            acc[n][2] = ffma2(xp[n], wb.x, acc[n][2]);
            acc[n][3] = ffma2(xp[n], wb.y, acc[n][3]);
        }
    }
    {
        float bv[8], aw[8];
        float4 t;
        t = __ldg((const float4*)(b1 + cg * 8));     bv[0]=t.x;bv[1]=t.y;bv[2]=t.z;bv[3]=t.w;
        t = __ldg((const float4*)(b1 + cg * 8 + 4)); bv[4]=t.x;bv[5]=t.y;bv[6]=t.z;bv[7]=t.w;
        t = __ldg((const float4*)(att_w + cg * 8));      aw[0]=t.x;aw[1]=t.y;aw[2]=t.z;aw[3]=t.w;
        t = __ldg((const float4*)(att_w + cg * 8 + 4));  aw[4]=t.x;aw[5]=t.y;aw[6]=t.z;aw[7]=t.w;
#pragma unroll
        for (int n = 0; n < 4; n++) {
            float s = 0.f;
#pragma unroll
            for (int j = 0; j < 4; j++) {
                float a, b;
                unpack2(acc[n][j], a, b);
                s += fmaxf(a + bv[2 * j], 0.f) * aw[2 * j]
                   + fmaxf(b + bv[2 * j + 1], 0.f) * aw[2 * j + 1];
            }
            p1[n] = s;
        }
    }

    // ================= pass B: X @ W2 =================
#pragma unroll
    for (int n = 0; n < 4; n++)
#pragma unroll
        for (int j = 0; j < 4; j++) acc[n][j] = 0ULL;

#pragma unroll 4
    for (int k = 0; k < 64; k++) {
        float4 xv = *(const float4*)(Xs + k * 128 + ng * 4);
        u64 xp[4];
        xp[0] = pack2(xv.x, xv.x);
        xp[1] = pack2(xv.y, xv.y);
        xp[2] = pack2(xv.z, xv.z);
        xp[3] = pack2(xv.w, xv.w);
        const float* wr = W2s + k * 64 + cg * 8;
        ulonglong2 wa = *(const ulonglong2*)(wr);
        ulonglong2 wb = *(const ulonglong2*)(wr + 4);
#pragma unroll
        for (int n = 0; n < 4; n++) {
            acc[n][0] = ffma2(xp[n], wa.x, acc[n][0]);
            acc[n][1] = ffma2(xp[n], wa.y, acc[n][1]);
            acc[n][2] = ffma2(xp[n], wb.x, acc[n][2]);
            acc[n][3] = ffma2(xp[n], wb.y, acc[n][3]);
        }
    }
    {
        float bv[8], aw[8];
        float4 t;
        t = __ldg((const float4*)(b2 + cg * 8));     bv[0]=t.x;bv[1]=t.y;bv[2]=t.z;bv[3]=t.w;
        t = __ldg((const float4*)(b2 + cg * 8 + 4)); bv[4]=t.x;bv[5]=t.y;bv[6]=t.z;bv[7]=t.w;
        t = __ldg((const float4*)(att_w + H + cg * 8));     aw[0]=t.x;aw[1]=t.y;aw[2]=t.z;aw[3]=t.w;
        t = __ldg((const float4*)(att_w + H + cg * 8 + 4)); aw[4]=t.x;aw[5]=t.y;aw[6]=t.z;aw[7]=t.w;
#pragma unroll
        for (int n = 0; n < 4; n++) {
            float s = 0.f;
#pragma unroll
            for (int j = 0; j < 4; j++) {
                float a, b;
                unpack2(acc[n][j], a, b);
                s += fmaxf(a + bv[2 * j], 0.f) * aw[2 * j]
                   + fmaxf(b + bv[2 * j + 1], 0.f) * aw[2 * j + 1];
            }
            p2[n] = s;
        }
    }

    // ---- cross-colgroup reduction via smem (reuse Xs) ----
    __syncthreads();
    float* red1 = Xs;           // [128 nodes][8 cg]
    float* red2 = Xs + 1024;
#pragma unroll
    for (int n = 0; n < 4; n++) {
        int nl = ng * 4 + n;
        red1[nl * 8 + cg] = p1[n];
        red2[nl * 8 + cg] = p2[n];
    }
    __syncthreads();

    if (tid < 128) {
        int node = tile + tid;
        if (node < N_NODES) {
            float s1 = 0.f, s2 = 0.f;
#pragma unroll
            for (int c = 0; c < 8; c++) { s1 += red1[tid * 8 + c]; s2 += red2[tid * 8 + c]; }
            g_s1[node] = s1;
            g_s2[node] = s2 + __ldg(att_b);
            g_rowsum[node] = 0.f;
        }
    }
}

// ------------------------------------------------------------------------
// Kernel 2: per-edge exp(att) + segment-sum; also zeroes out_part
// (exactly one float4 per thread: 800k threads x 4 = 3.2M floats = N*H).
// ------------------------------------------------------------------------
__global__ __launch_bounds__(256)
void gat_edge_att_kernel(const int* __restrict__ edge_index,
                         float* __restrict__ out_part) {
    int e = blockIdx.x * blockDim.x + threadIdx.x;
    if (e >= N_EDGES) return;

    ((float4*)out_part)[e] = make_float4(0.f, 0.f, 0.f, 0.f);

    int r = __ldg(edge_index + e);
    int c = __ldg(edge_index + N_EDGES + e);
    float ea = __expf(__ldg(g_s1 + r) + __ldg(g_s2 + c));
    g_expatt[e] = ea;
    atomicAdd(&g_rowsum[r], ea);
}

// ------------------------------------------------------------------------
// Kernel 3: per-edge value + SpMM scatter (16 threads/edge, float4 red).
// ------------------------------------------------------------------------
__global__ __launch_bounds__(256)
void gat_edge_spmm_kernel(const int* __restrict__ edge_index,
                          const float* __restrict__ adj_values,
                          const float* __restrict__ embeds,
                          float* __restrict__ values,
                          float* __restrict__ out_part) {
    unsigned gid = blockIdx.x * blockDim.x + threadIdx.x;
    unsigned e = gid >> 4;
    if (e >= N_EDGES) return;
    unsigned sub = gid & 15u;

    int r = __ldg(edge_index + e);
    int c = __ldg(edge_index + N_EDGES + e);
    float ea = __ldg(g_expatt + e);
    float rs = __ldg(g_rowsum + r) + 1e-6f;
    float v = (ea / rs + RES * __ldg(adj_values + e)) * INV_1PRES;
    if (sub == 0) values[e] = v;

    float4 ev = __ldg((const float4*)(embeds + (size_t)c * H + sub * 4));
    float* dst = out_part + (size_t)r * H + sub * 4;
    asm volatile("red.global.add.v4.f32 [%0], {%1, %2, %3, %4};"
                 :: "l"(dst), "f"(ev.x * v), "f"(ev.y * v), "f"(ev.z * v), "f"(ev.w * v)
                 : "memory");
}

// ------------------------------------------------------------------------
extern "C" void kernel_launch(void* const* d_in, const int* in_sizes, int n_in,
                              void* d_out, int out_size) {
    const int*   edge_index = (const int*)d_in[0];
    const float* adj_values = (const float*)d_in[1];
    const float* embeds     = (const float*)d_in[2];
    const float* W1         = (const float*)d_in[3];
    const float* b1         = (const float*)d_in[4];
    const float* W2         = (const float*)d_in[5];
    const float* b2         = (const float*)d_in[6];
    const float* att_w      = (const float*)d_in[7];
    const float* att_b      = (const float*)d_in[8];

    float* values   = (float*)d_out;            // [E]
    float* out_part = (float*)d_out + N_EDGES;  // [N, H]

    static bool attr_done = false;
    if (!attr_done) {
        cudaFuncSetAttribute(gat_node_kernel,
                             cudaFuncAttributeMaxDynamicSharedMemorySize, 65536);
        attr_done = true;
    }

    gat_node_kernel<<<(N_NODES + 127) / 128, 256, 65536>>>(
        embeds, W1, b1, W2, b2, att_w, att_b);

    gat_edge_att_kernel<<<(N_EDGES + 255) / 256, 256>>>(edge_index, out_part);

    gat_edge_spmm_kernel<<<(N_EDGES * 16 + 255) / 256, 256>>>(
        edge_index, adj_values, embeds, values, out_part);
}